// round 1
// baseline (speedup 1.0000x reference)
#include <cuda_runtime.h>

#define BB 2
#define SS 2048
#define DD 1024
#define HH 16
#define DKK 64
#define KSPLIT 16

// ---------------- device scratch (static globals; no allocations) ----------------
__device__ float g_qs[(size_t)BB*HH*SS*DKK];   // Q projections, pre-scaled by log2e/sqrt(dk)
__device__ float g_ks[(size_t)BB*HH*SS*DKK];   // K projections
__device__ float g_vs[(size_t)BB*SS*DKK];      // shared V projection
__device__ float g_w [(size_t)BB*HH*SS];       // 1/(H * rowsum_h(s))
__device__ float g_headp[(size_t)KSPLIT*BB*SS*DKK]; // split-K partials of attn_mean @ vs
__device__ float g_head [(size_t)BB*SS*DKK];

// ---------------- fast exp2 on the FMA pipe (avoids MUFU bottleneck) -------------
__device__ __forceinline__ float fast_exp2(float x) {
    float n = rintf(x);
    float f = x - n;
    // Taylor for 2^f on [-0.5, 0.5]; max rel err ~3e-6
    float p = 1.5403530e-4f;
    p = fmaf(p, f, 1.3333558e-3f);
    p = fmaf(p, f, 9.6181291e-3f);
    p = fmaf(p, f, 5.5504109e-2f);
    p = fmaf(p, f, 2.4022650e-1f);
    p = fmaf(p, f, 6.9314718e-1f);
    p = fmaf(p, f, 1.0f);
    int e = (int)n;
    return p * __int_as_float((e + 127) << 23);
}

// Load a 64x64 fp32 tile (row stride 64 in gmem) transposed into smem dst[k][row].
__device__ __forceinline__ void load_tile64_T(float dst[64][64], const float* __restrict__ src, int tid) {
    #pragma unroll
    for (int l = 0; l < 4; l++) {
        int f   = tid + l * 256;       // float4 index 0..1023
        int row = f >> 4;
        int c4  = (f & 15) * 4;
        float4 x = *(const float4*)&src[(size_t)row * 64 + c4];
        dst[c4 + 0][row] = x.x;
        dst[c4 + 1][row] = x.y;
        dst[c4 + 2][row] = x.z;
        dst[c4 + 3][row] = x.w;
    }
}

// ---------------- K1: projections qs = (q@Wq[h])*log2e/8, ks = k@Wk[h], vs = v@Wv -
// grid: x = s_tile(32), y = h(16), z = kind*BB + b  (kind 0=q,1=k,2=v)
__global__ void k_proj(const float* __restrict__ q, const float* __restrict__ k,
                       const float* __restrict__ v, const float* __restrict__ Wq,
                       const float* __restrict__ Wk, const float* __restrict__ Wv) {
    int kind = blockIdx.z >> 1;
    int b    = blockIdx.z & 1;
    int h    = blockIdx.y;
    if (kind == 2 && h != 0) return;
    int s0 = blockIdx.x * 64;

    const float* A; const float* W; float* C; float scale;
    if (kind == 0)      { A = q + (size_t)b*SS*DD; W = Wq + (size_t)h*DD*DKK;
                          C = g_qs + ((size_t)(b*HH + h)*SS) * DKK; scale = 1.4426950408889634f / 8.0f; }
    else if (kind == 1) { A = k + (size_t)b*SS*DD; W = Wk + (size_t)h*DD*DKK;
                          C = g_ks + ((size_t)(b*HH + h)*SS) * DKK; scale = 1.0f; }
    else                { A = v + (size_t)b*SS*DD; W = Wv;
                          C = g_vs + (size_t)b*SS*DKK; scale = 1.0f; }

    __shared__ float As[16][64];   // [k][row]
    __shared__ float Ws[16][64];   // [k][col]
    int tid = threadIdx.x;
    int tx = tid & 15, ty = tid >> 4;
    float acc[4][4] = {};

    for (int k0 = 0; k0 < DD; k0 += 16) {
        {   // A tile: 64 rows x 16 cols, transposed store
            int row = tid >> 2;
            int kk4 = (tid & 3) * 4;
            float4 av = *(const float4*)&A[(size_t)(s0 + row) * DD + k0 + kk4];
            As[kk4 + 0][row] = av.x; As[kk4 + 1][row] = av.y;
            As[kk4 + 2][row] = av.z; As[kk4 + 3][row] = av.w;
        }
        {   // W tile: 16 rows x 64 cols, direct
            int kk = tid >> 4;
            int c4 = (tid & 15) * 4;
            *(float4*)&Ws[kk][c4] = *(const float4*)&W[(size_t)(k0 + kk) * DKK + c4];
        }
        __syncthreads();
        #pragma unroll
        for (int kk = 0; kk < 16; kk++) {
            float4 a  = *(const float4*)&As[kk][ty * 4];
            float4 bb = *(const float4*)&Ws[kk][tx * 4];
            float av[4] = {a.x, a.y, a.z, a.w};
            float bv[4] = {bb.x, bb.y, bb.z, bb.w};
            #pragma unroll
            for (int i = 0; i < 4; i++)
                #pragma unroll
                for (int j = 0; j < 4; j++)
                    acc[i][j] = fmaf(av[i], bv[j], acc[i][j]);
        }
        __syncthreads();
    }
    #pragma unroll
    for (int i = 0; i < 4; i++) {
        float4 o;
        o.x = acc[i][0] * scale; o.y = acc[i][1] * scale;
        o.z = acc[i][2] * scale; o.w = acc[i][3] * scale;
        *(float4*)&C[(size_t)(s0 + ty * 4 + i) * DKK + tx * 4] = o;
    }
}

// ---------------- K2: pass 1 — row sums of exp(scores) per (b,h,s) ----------------
// grid: x = s_tile(32), y = h, z = b
__global__ void k_rowsum() {
    int b = blockIdx.z, h = blockIdx.y;
    int s0 = blockIdx.x * 64;
    const float* Q = g_qs + ((size_t)(b*HH + h)*SS + s0) * DKK;
    const float* K = g_ks + ((size_t)(b*HH + h)*SS) * DKK;

    __shared__ float Qs[64][64];
    __shared__ float Ks[64][64];
    __shared__ float red[64][17];
    int tid = threadIdx.x;
    int tx = tid & 15, ty = tid >> 4;

    load_tile64_T(Qs, Q, tid);
    __syncthreads();

    float rsum[4] = {0.f, 0.f, 0.f, 0.f};
    for (int t0 = 0; t0 < SS; t0 += 64) {
        load_tile64_T(Ks, K + (size_t)t0 * DKK, tid);
        __syncthreads();
        float sc[4][4] = {};
        #pragma unroll 16
        for (int kk = 0; kk < 64; kk++) {
            float4 a  = *(const float4*)&Qs[kk][ty * 4];
            float4 bb = *(const float4*)&Ks[kk][tx * 4];
            float av[4] = {a.x, a.y, a.z, a.w};
            float bv[4] = {bb.x, bb.y, bb.z, bb.w};
            #pragma unroll
            for (int i = 0; i < 4; i++)
                #pragma unroll
                for (int j = 0; j < 4; j++)
                    sc[i][j] = fmaf(av[i], bv[j], sc[i][j]);
        }
        #pragma unroll
        for (int i = 0; i < 4; i++)
            #pragma unroll
            for (int j = 0; j < 4; j++)
                rsum[i] += fast_exp2(sc[i][j]);
        __syncthreads();
    }
    #pragma unroll
    for (int i = 0; i < 4; i++) red[ty * 4 + i][tx] = rsum[i];
    __syncthreads();
    if (tid < 64) {
        float s = 0.f;
        #pragma unroll
        for (int t = 0; t < 16; t++) s += red[tid][t];
        g_w[(size_t)(b*HH + h)*SS + s0 + tid] = 1.0f / (s * (float)HH);
    }
}

// ---------------- K3: pass 2 — attn_mean tile, summed over all heads --------------
// grid: x = t_tile(32), y = s_tile(32), z = b
__global__ void k_attn(float* __restrict__ out) {
    int b = blockIdx.z;
    int s0 = blockIdx.y * 64;
    int t0 = blockIdx.x * 64;
    __shared__ float Qs[64][64];
    __shared__ float Ks[64][64];
    int tid = threadIdx.x;
    int tx = tid & 15, ty = tid >> 4;

    float acc[4][4] = {};
    for (int h = 0; h < HH; h++) {
        const float* Q = g_qs + ((size_t)(b*HH + h)*SS + s0) * DKK;
        const float* K = g_ks + ((size_t)(b*HH + h)*SS + t0) * DKK;
        load_tile64_T(Qs, Q, tid);
        load_tile64_T(Ks, K, tid);
        __syncthreads();
        float sc[4][4] = {};
        #pragma unroll 16
        for (int kk = 0; kk < 64; kk++) {
            float4 a  = *(const float4*)&Qs[kk][ty * 4];
            float4 bb = *(const float4*)&Ks[kk][tx * 4];
            float av[4] = {a.x, a.y, a.z, a.w};
            float bv[4] = {bb.x, bb.y, bb.z, bb.w};
            #pragma unroll
            for (int i = 0; i < 4; i++)
                #pragma unroll
                for (int j = 0; j < 4; j++)
                    sc[i][j] = fmaf(av[i], bv[j], sc[i][j]);
        }
        float wrow[4];
        #pragma unroll
        for (int i = 0; i < 4; i++)
            wrow[i] = g_w[(size_t)(b*HH + h)*SS + s0 + ty * 4 + i];
        #pragma unroll
        for (int i = 0; i < 4; i++)
            #pragma unroll
            for (int j = 0; j < 4; j++)
                acc[i][j] = fmaf(fast_exp2(sc[i][j]), wrow[i], acc[i][j]);
        __syncthreads();
    }
    float* AM = out + (size_t)BB*SS*DD + ((size_t)b*SS + s0) * SS + t0;
    #pragma unroll
    for (int i = 0; i < 4; i++) {
        float4 o; o.x = acc[i][0]; o.y = acc[i][1]; o.z = acc[i][2]; o.w = acc[i][3];
        *(float4*)&AM[(size_t)(ty * 4 + i) * SS + tx * 4] = o;
    }
}

// ---------------- K4: head partials = attn_mean @ vs (split-K, deterministic) -----
// grid: x = c (16 K-chunks of 128), y = s_tile(32), z = b
__global__ void k_headp(const float* __restrict__ out) {
    int c = blockIdx.x;
    int s0 = blockIdx.y * 64;
    int b = blockIdx.z;
    int tb = c * (SS / KSPLIT);   // 128-wide t chunk

    const float* AM = out + (size_t)BB*SS*DD + ((size_t)b*SS) * SS;
    const float* V  = g_vs + (size_t)b*SS*DKK;

    __shared__ float As[16][64];   // [t][row]
    __shared__ float Vs[16][64];   // [t][k]
    int tid = threadIdx.x;
    int tx = tid & 15, ty = tid >> 4;
    float acc[4][4] = {};

    for (int t0 = 0; t0 < SS / KSPLIT; t0 += 16) {
        {
            int row = tid >> 2;
            int kk4 = (tid & 3) * 4;
            float4 av = *(const float4*)&AM[(size_t)(s0 + row) * SS + tb + t0 + kk4];
            As[kk4 + 0][row] = av.x; As[kk4 + 1][row] = av.y;
            As[kk4 + 2][row] = av.z; As[kk4 + 3][row] = av.w;
        }
        {
            int kk = tid >> 4;
            int c4 = (tid & 15) * 4;
            *(float4*)&Vs[kk][c4] = *(const float4*)&V[(size_t)(tb + t0 + kk) * DKK + c4];
        }
        __syncthreads();
        #pragma unroll
        for (int kk = 0; kk < 16; kk++) {
            float4 a  = *(const float4*)&As[kk][ty * 4];
            float4 bb = *(const float4*)&Vs[kk][tx * 4];
            float av[4] = {a.x, a.y, a.z, a.w};
            float bv[4] = {bb.x, bb.y, bb.z, bb.w};
            #pragma unroll
            for (int i = 0; i < 4; i++)
                #pragma unroll
                for (int j = 0; j < 4; j++)
                    acc[i][j] = fmaf(av[i], bv[j], acc[i][j]);
        }
        __syncthreads();
    }
    float* C = g_headp + (((size_t)c*BB + b)*SS) * DKK;
    #pragma unroll
    for (int i = 0; i < 4; i++) {
        float4 o; o.x = acc[i][0]; o.y = acc[i][1]; o.z = acc[i][2]; o.w = acc[i][3];
        *(float4*)&C[(size_t)(s0 + ty * 4 + i) * DKK + tx * 4] = o;
    }
}

// ---------------- K5: reduce split-K partials -------------------------------------
__global__ void k_reduce() {
    size_t i4 = (size_t)blockIdx.x * blockDim.x + threadIdx.x;   // float4 index
    size_t N4 = (size_t)BB*SS*DKK / 4;
    if (i4 >= N4) return;
    float4 s = make_float4(0.f, 0.f, 0.f, 0.f);
    #pragma unroll
    for (int c = 0; c < KSPLIT; c++) {
        float4 x = *((const float4*)g_headp + (size_t)c * N4 + i4);
        s.x += x.x; s.y += x.y; s.z += x.z; s.w += x.w;
    }
    *((float4*)g_head + i4) = s;
}

// ---------------- K6: out = head @ Wo ---------------------------------------------
// grid: x = d_tile(16), y = row_tile(64) over B*S rows
__global__ void k_out(const float* __restrict__ Wo, float* __restrict__ out) {
    int d0 = blockIdx.x * 64;
    int r0 = blockIdx.y * 64;
    __shared__ float Hs[64][64];   // [k][row]
    __shared__ float Ws[64][64];   // [k][d]
    int tid = threadIdx.x;
    int tx = tid & 15, ty = tid >> 4;

    load_tile64_T(Hs, g_head + (size_t)r0 * DKK, tid);
    #pragma unroll
    for (int l = 0; l < 4; l++) {
        int f  = tid + l * 256;
        int kk = f >> 4;
        int c4 = (f & 15) * 4;
        *(float4*)&Ws[kk][c4] = *(const float4*)&Wo[(size_t)kk * DD + d0 + c4];
    }
    __syncthreads();

    float acc[4][4] = {};
    #pragma unroll 16
    for (int kk = 0; kk < 64; kk++) {
        float4 a  = *(const float4*)&Hs[kk][ty * 4];
        float4 bb = *(const float4*)&Ws[kk][tx * 4];
        float av[4] = {a.x, a.y, a.z, a.w};
        float bv[4] = {bb.x, bb.y, bb.z, bb.w};
        #pragma unroll
        for (int i = 0; i < 4; i++)
            #pragma unroll
            for (int j = 0; j < 4; j++)
                acc[i][j] = fmaf(av[i], bv[j], acc[i][j]);
    }
    #pragma unroll
    for (int i = 0; i < 4; i++) {
        float4 o; o.x = acc[i][0]; o.y = acc[i][1]; o.z = acc[i][2]; o.w = acc[i][3];
        *(float4*)&out[(size_t)(r0 + ty * 4 + i) * DD + d0 + tx * 4] = o;
    }
}

// ---------------- launch ----------------------------------------------------------
extern "C" void kernel_launch(void* const* d_in, const int* in_sizes, int n_in,
                              void* d_out, int out_size) {
    const float* q  = (const float*)d_in[0];
    const float* k  = (const float*)d_in[1];
    const float* v  = (const float*)d_in[2];
    const float* Wq = (const float*)d_in[3];
    const float* Wk = (const float*)d_in[4];
    const float* Wv = (const float*)d_in[5];
    const float* Wo = (const float*)d_in[6];
    float* out = (float*)d_out;

    dim3 gp(SS / 64, HH, 3 * BB);
    k_proj<<<gp, 256>>>(q, k, v, Wq, Wk, Wv);

    dim3 gr(SS / 64, HH, BB);
    k_rowsum<<<gr, 256>>>();

    dim3 ga(SS / 64, SS / 64, BB);
    k_attn<<<ga, 256>>>(out);

    dim3 gh(KSPLIT, SS / 64, BB);
    k_headp<<<gh, 256>>>(out);

    int n4 = BB * SS * DKK / 4;
    k_reduce<<<(n4 + 255) / 256, 256>>>();

    dim3 go(DD / 64, BB * SS / 64);
    k_out<<<go, 256>>>(Wo, out);
}

// round 2
// speedup vs baseline: 3.7875x; 3.7875x over previous
#include <cuda_runtime.h>

#define BB 2
#define SS 2048
#define DD 1024
#define HH 16
#define DKK 64
#define KSPLIT 16

// ---------------- device scratch ----------------
__device__ float g_qs[(size_t)BB*HH*SS*DKK];   // tf32-rounded, scaled by log2e/8
__device__ float g_ks[(size_t)BB*HH*SS*DKK];   // tf32-rounded
__device__ float g_vs[(size_t)BB*SS*DKK];
__device__ float g_w [(size_t)BB*HH*SS];       // 1/(H * rowsum)
__device__ float g_headp[(size_t)KSPLIT*BB*SS*DKK];
__device__ float g_head [(size_t)BB*SS*DKK];

// ---------------- helpers ----------------
__device__ __forceinline__ float ex2(float x) {
    float y; asm("ex2.approx.f32 %0, %1;" : "=f"(y) : "f"(x)); return y;
}
__device__ __forceinline__ float to_tf32(float x) {
    unsigned u; asm("cvt.rna.tf32.f32 %0, %1;" : "=r"(u) : "f"(x));
    return __uint_as_float(u);
}
__device__ __forceinline__ void mma_tf32(float c[4], const unsigned a[4], const unsigned b[2]) {
    asm volatile(
        "mma.sync.aligned.m16n8k8.row.col.f32.tf32.tf32.f32 "
        "{%0,%1,%2,%3}, {%4,%5,%6,%7}, {%8,%9}, {%0,%1,%2,%3};\n"
        : "+f"(c[0]), "+f"(c[1]), "+f"(c[2]), "+f"(c[3])
        : "r"(a[0]), "r"(a[1]), "r"(a[2]), "r"(a[3]), "r"(b[0]), "r"(b[1]));
}

// ================= K1: Q/K projections as dense GEMM (tf32 MMA) =================
// C[2048,1024] = A[2048,1024] @ Wcat[1024,1024];  n = h*64+dk
// grid: x = n_tile(8, 128 cols = 2 heads), y = m_tile(16, 128 rows), z = kind*2+b
__global__ void k_proj_mma(const float* __restrict__ q, const float* __restrict__ k,
                           const float* __restrict__ Wq, const float* __restrict__ Wk) {
    extern __shared__ float sm[];
    float (*As)[36]  = (float(*)[36])sm;            // [128][36]
    float (*Bs)[136] = (float(*)[136])(sm + 128*36); // [32][136]

    int kind = blockIdx.z >> 1;
    int b    = blockIdx.z & 1;
    int h0   = blockIdx.x * 2;
    int s0   = blockIdx.y * 128;

    const float* A = (kind ? k : q) + (size_t)b*SS*DD;
    const float* W = kind ? Wk : Wq;
    float* C       = kind ? g_ks : g_qs;
    float scale    = kind ? 1.0f : (1.4426950408889634f / 8.0f);

    int tid = threadIdx.x;
    int w = tid >> 5, lane = tid & 31;
    int wm = w >> 1, wn = w & 1;
    int g = lane >> 2, tg = lane & 3;

    float c[2][8][4] = {};

    for (int k0 = 0; k0 < DD; k0 += 32) {
        #pragma unroll
        for (int i = 0; i < 4; i++) {                 // A: 128x32
            int f = tid + i * 256;
            int row = f >> 3, c4 = (f & 7) * 4;
            *(float4*)&As[row][c4] = *(const float4*)&A[(size_t)(s0 + row) * DD + k0 + c4];
        }
        #pragma unroll
        for (int i = 0; i < 4; i++) {                 // B: 32x128 (2 heads wide)
            int f = tid + i * 256;
            int kk = f >> 5, n4 = (f & 31) * 4;
            int hh = h0 + (n4 >> 6), dk = n4 & 63;
            *(float4*)&Bs[kk][n4] = *(const float4*)&W[((size_t)hh * DD + k0 + kk) * DKK + dk];
        }
        __syncthreads();
        #pragma unroll
        for (int ks = 0; ks < 32; ks += 8) {
            unsigned a[2][4];
            #pragma unroll
            for (int mf = 0; mf < 2; mf++) {
                int r = wm * 32 + mf * 16 + g;
                a[mf][0] = __float_as_uint(As[r    ][ks + tg]);
                a[mf][1] = __float_as_uint(As[r + 8][ks + tg]);
                a[mf][2] = __float_as_uint(As[r    ][ks + tg + 4]);
                a[mf][3] = __float_as_uint(As[r + 8][ks + tg + 4]);
            }
            unsigned bfr[8][2];
            #pragma unroll
            for (int nf = 0; nf < 8; nf++) {
                int n = wn * 64 + nf * 8 + g;
                bfr[nf][0] = __float_as_uint(Bs[ks + tg    ][n]);
                bfr[nf][1] = __float_as_uint(Bs[ks + tg + 4][n]);
            }
            #pragma unroll
            for (int mf = 0; mf < 2; mf++)
                #pragma unroll
                for (int nf = 0; nf < 8; nf++)
                    mma_tf32(c[mf][nf], a[mf], bfr[nf]);
        }
        __syncthreads();
    }
    // store, tf32-rounded so both score passes see identical operands
    int hh = h0 + wn;
    #pragma unroll
    for (int mf = 0; mf < 2; mf++) {
        int r = s0 + wm * 32 + mf * 16 + g;
        #pragma unroll
        for (int nf = 0; nf < 8; nf++) {
            int dk = nf * 8 + 2 * tg;
            float* p0 = &C[((size_t)(b * HH + hh) * SS + r) * DKK + dk];
            float* p1 = &C[((size_t)(b * HH + hh) * SS + r + 8) * DKK + dk];
            float2 o0 = make_float2(to_tf32(c[mf][nf][0] * scale), to_tf32(c[mf][nf][1] * scale));
            float2 o1 = make_float2(to_tf32(c[mf][nf][2] * scale), to_tf32(c[mf][nf][3] * scale));
            *(float2*)p0 = o0;
            *(float2*)p1 = o1;
        }
    }
}

// ================= K1b: V projection (small, SIMT) =================
// grid: x = s_tile(32), z = b
__global__ void k_projv(const float* __restrict__ v, const float* __restrict__ Wv) {
    int b  = blockIdx.z;
    int s0 = blockIdx.x * 64;
    const float* A = v + (size_t)b*SS*DD;
    float* C = g_vs + (size_t)b*SS*DKK;

    __shared__ float As[16][64];
    __shared__ float Ws[16][64];
    int tid = threadIdx.x;
    int tx = tid & 15, ty = tid >> 4;
    float acc[4][4] = {};

    for (int k0 = 0; k0 < DD; k0 += 16) {
        {
            int row = tid >> 2, kk4 = (tid & 3) * 4;
            float4 av = *(const float4*)&A[(size_t)(s0 + row) * DD + k0 + kk4];
            As[kk4+0][row] = av.x; As[kk4+1][row] = av.y;
            As[kk4+2][row] = av.z; As[kk4+3][row] = av.w;
        }
        {
            int kk = tid >> 4, c4 = (tid & 15) * 4;
            *(float4*)&Ws[kk][c4] = *(const float4*)&Wv[(size_t)(k0 + kk) * DKK + c4];
        }
        __syncthreads();
        #pragma unroll
        for (int kk = 0; kk < 16; kk++) {
            float4 a  = *(const float4*)&As[kk][ty * 4];
            float4 bb = *(const float4*)&Ws[kk][tx * 4];
            float av[4] = {a.x, a.y, a.z, a.w};
            float bv[4] = {bb.x, bb.y, bb.z, bb.w};
            #pragma unroll
            for (int i = 0; i < 4; i++)
                #pragma unroll
                for (int j = 0; j < 4; j++)
                    acc[i][j] = fmaf(av[i], bv[j], acc[i][j]);
        }
        __syncthreads();
    }
    #pragma unroll
    for (int i = 0; i < 4; i++) {
        float4 o; o.x = acc[i][0]; o.y = acc[i][1]; o.z = acc[i][2]; o.w = acc[i][3];
        *(float4*)&C[(size_t)(s0 + ty * 4 + i) * DKK + tx * 4] = o;
    }
}

// ---- shared tile loaders for score kernels ----
__device__ __forceinline__ void load_q128(float (*Qs)[68], const float* src, int tid) {
    #pragma unroll
    for (int i = 0; i < 8; i++) {
        int f = tid + i * 256;
        int row = f >> 4, c4 = (f & 15) * 4;
        *(float4*)&Qs[row][c4] = *(const float4*)&src[(size_t)row * DKK + c4];
    }
}
__device__ __forceinline__ void load_k64(float (*Ks)[68], const float* src, int tid) {
    #pragma unroll
    for (int i = 0; i < 4; i++) {
        int f = tid + i * 256;
        int row = f >> 4, c4 = (f & 15) * 4;
        *(float4*)&Ks[row][c4] = *(const float4*)&src[(size_t)row * DKK + c4];
    }
}
// one 128x64 score tile: 8 warps (4m x 2n), warp tile 32x32, frags c[2][4][4]
__device__ __forceinline__ void qk_tile(const float (*Qs)[68], const float (*Ks)[68],
                                        int wm, int wn, int g, int tg, float c[2][4][4]) {
    #pragma unroll
    for (int ks = 0; ks < 64; ks += 8) {
        unsigned a[2][4];
        #pragma unroll
        for (int mf = 0; mf < 2; mf++) {
            int r = wm * 32 + mf * 16 + g;
            a[mf][0] = __float_as_uint(Qs[r    ][ks + tg]);
            a[mf][1] = __float_as_uint(Qs[r + 8][ks + tg]);
            a[mf][2] = __float_as_uint(Qs[r    ][ks + tg + 4]);
            a[mf][3] = __float_as_uint(Qs[r + 8][ks + tg + 4]);
        }
        unsigned bfr[4][2];
        #pragma unroll
        for (int nf = 0; nf < 4; nf++) {
            int t = wn * 32 + nf * 8 + g;
            bfr[nf][0] = __float_as_uint(Ks[t][ks + tg]);
            bfr[nf][1] = __float_as_uint(Ks[t][ks + tg + 4]);
        }
        #pragma unroll
        for (int mf = 0; mf < 2; mf++)
            #pragma unroll
            for (int nf = 0; nf < 4; nf++)
                mma_tf32(c[mf][nf], a[mf], bfr[nf]);
    }
}

// ================= K2: pass 1 — rowsums of exp2(scores) =================
// grid: x = s_tile(16, 128 rows), y = h, z = b
__global__ void k_rowsum() {
    extern __shared__ float sm[];
    float (*Qs)[68] = (float(*)[68])sm;
    float (*Ks)[68] = (float(*)[68])(sm + 128*68);
    float* red      = sm + 128*68 + 64*68;          // [2][128]

    int b = blockIdx.z, h = blockIdx.y;
    int s0 = blockIdx.x * 128;
    int tid = threadIdx.x;
    int w = tid >> 5, lane = tid & 31;
    int wm = w >> 1, wn = w & 1;
    int g = lane >> 2, tg = lane & 3;

    load_q128(Qs, g_qs + ((size_t)(b*HH + h)*SS + s0) * DKK, tid);

    float rs[2][2] = {};
    const float* Kbase = g_ks + ((size_t)(b*HH + h)*SS) * DKK;
    for (int t0 = 0; t0 < SS; t0 += 64) {
        __syncthreads();
        load_k64(Ks, Kbase + (size_t)t0 * DKK, tid);
        __syncthreads();
        float c[2][4][4] = {};
        qk_tile(Qs, Ks, wm, wn, g, tg, c);
        #pragma unroll
        for (int mf = 0; mf < 2; mf++)
            #pragma unroll
            for (int nf = 0; nf < 4; nf++) {
                rs[mf][0] += ex2(c[mf][nf][0]) + ex2(c[mf][nf][1]);
                rs[mf][1] += ex2(c[mf][nf][2]) + ex2(c[mf][nf][3]);
            }
    }
    // reduce over tg (4 lanes share a row)
    #pragma unroll
    for (int mf = 0; mf < 2; mf++)
        #pragma unroll
        for (int i = 0; i < 2; i++) {
            float s = rs[mf][i];
            s += __shfl_xor_sync(0xffffffffu, s, 1);
            s += __shfl_xor_sync(0xffffffffu, s, 2);
            rs[mf][i] = s;
        }
    __syncthreads();
    if (tg == 0) {
        #pragma unroll
        for (int mf = 0; mf < 2; mf++)
            #pragma unroll
            for (int i = 0; i < 2; i++)
                red[wn * 128 + wm * 32 + mf * 16 + g + 8 * i] = rs[mf][i];
    }
    __syncthreads();
    if (tid < 128) {
        float s = red[tid] + red[128 + tid];
        g_w[(size_t)(b*HH + h)*SS + s0 + tid] = 1.0f / (s * (float)HH);
    }
}

// ================= K3: pass 2 — attn_mean (head-summed, normalized) =================
// grid: x = t_tile(32, 64 cols), y = s_tile(16, 128 rows), z = b
__global__ void k_attn(float* __restrict__ out) {
    extern __shared__ float sm[];
    float (*Qs)[68] = (float(*)[68])sm;
    float (*Ks)[68] = (float(*)[68])(sm + 128*68);

    int b = blockIdx.z;
    int s0 = blockIdx.y * 128;
    int t0 = blockIdx.x * 64;
    int tid = threadIdx.x;
    int w = tid >> 5, lane = tid & 31;
    int wm = w >> 1, wn = w & 1;
    int g = lane >> 2, tg = lane & 3;

    float acc[2][4][4] = {};

    for (int h = 0; h < HH; h++) {
        load_q128(Qs, g_qs + ((size_t)(b*HH + h)*SS + s0) * DKK, tid);
        load_k64(Ks, g_ks + ((size_t)(b*HH + h)*SS + t0) * DKK, tid);
        __syncthreads();
        float c[2][4][4] = {};
        qk_tile(Qs, Ks, wm, wn, g, tg, c);
        float wv[2][2];
        #pragma unroll
        for (int mf = 0; mf < 2; mf++) {
            int r = s0 + wm * 32 + mf * 16 + g;
            wv[mf][0] = g_w[(size_t)(b*HH + h)*SS + r];
            wv[mf][1] = g_w[(size_t)(b*HH + h)*SS + r + 8];
        }
        #pragma unroll
        for (int mf = 0; mf < 2; mf++)
            #pragma unroll
            for (int nf = 0; nf < 4; nf++) {
                acc[mf][nf][0] = fmaf(ex2(c[mf][nf][0]), wv[mf][0], acc[mf][nf][0]);
                acc[mf][nf][1] = fmaf(ex2(c[mf][nf][1]), wv[mf][0], acc[mf][nf][1]);
                acc[mf][nf][2] = fmaf(ex2(c[mf][nf][2]), wv[mf][1], acc[mf][nf][2]);
                acc[mf][nf][3] = fmaf(ex2(c[mf][nf][3]), wv[mf][1], acc[mf][nf][3]);
            }
        __syncthreads();
    }
    float* AM = out + (size_t)BB*SS*DD + ((size_t)b*SS) * SS;
    #pragma unroll
    for (int mf = 0; mf < 2; mf++) {
        int r = s0 + wm * 32 + mf * 16 + g;
        #pragma unroll
        for (int nf = 0; nf < 4; nf++) {
            int cc = t0 + wn * 32 + nf * 8 + 2 * tg;
            *(float2*)&AM[(size_t)r * SS + cc]       = make_float2(acc[mf][nf][0], acc[mf][nf][1]);
            *(float2*)&AM[(size_t)(r + 8) * SS + cc] = make_float2(acc[mf][nf][2], acc[mf][nf][3]);
        }
    }
}

// ================= K4: head partials = attn_mean @ vs (split-K) =================
__global__ void k_headp(const float* __restrict__ out) {
    int c = blockIdx.x;
    int s0 = blockIdx.y * 64;
    int b = blockIdx.z;
    int tb = c * (SS / KSPLIT);

    const float* AM = out + (size_t)BB*SS*DD + ((size_t)b*SS) * SS;
    const float* V  = g_vs + (size_t)b*SS*DKK;

    __shared__ float As[16][64];
    __shared__ float Vs[16][64];
    int tid = threadIdx.x;
    int tx = tid & 15, ty = tid >> 4;
    float acc[4][4] = {};

    for (int t0 = 0; t0 < SS / KSPLIT; t0 += 16) {
        {
            int row = tid >> 2, kk4 = (tid & 3) * 4;
            float4 av = *(const float4*)&AM[(size_t)(s0 + row) * SS + tb + t0 + kk4];
            As[kk4+0][row] = av.x; As[kk4+1][row] = av.y;
            As[kk4+2][row] = av.z; As[kk4+3][row] = av.w;
        }
        {
            int kk = tid >> 4, c4 = (tid & 15) * 4;
            *(float4*)&Vs[kk][c4] = *(const float4*)&V[(size_t)(tb + t0 + kk) * DKK + c4];
        }
        __syncthreads();
        #pragma unroll
        for (int kk = 0; kk < 16; kk++) {
            float4 a  = *(const float4*)&As[kk][ty * 4];
            float4 bb = *(const float4*)&Vs[kk][tx * 4];
            float av[4] = {a.x, a.y, a.z, a.w};
            float bv[4] = {bb.x, bb.y, bb.z, bb.w};
            #pragma unroll
            for (int i = 0; i < 4; i++)
                #pragma unroll
                for (int j = 0; j < 4; j++)
                    acc[i][j] = fmaf(av[i], bv[j], acc[i][j]);
        }
        __syncthreads();
    }
    float* C = g_headp + (((size_t)c*BB + b)*SS) * DKK;
    #pragma unroll
    for (int i = 0; i < 4; i++) {
        float4 o; o.x = acc[i][0]; o.y = acc[i][1]; o.z = acc[i][2]; o.w = acc[i][3];
        *(float4*)&C[(size_t)(s0 + ty * 4 + i) * DKK + tx * 4] = o;
    }
}

// ================= K5: reduce split-K partials =================
__global__ void k_reduce() {
    size_t i4 = (size_t)blockIdx.x * blockDim.x + threadIdx.x;
    size_t N4 = (size_t)BB*SS*DKK / 4;
    if (i4 >= N4) return;
    float4 s = make_float4(0.f, 0.f, 0.f, 0.f);
    #pragma unroll
    for (int c = 0; c < KSPLIT; c++) {
        float4 x = *((const float4*)g_headp + (size_t)c * N4 + i4);
        s.x += x.x; s.y += x.y; s.z += x.z; s.w += x.w;
    }
    *((float4*)g_head + i4) = s;
}

// ================= K6: out = head @ Wo =================
__global__ void k_out(const float* __restrict__ Wo, float* __restrict__ out) {
    int d0 = blockIdx.x * 64;
    int r0 = blockIdx.y * 64;
    __shared__ float Hs[64][64];
    __shared__ float Ws[64][64];
    int tid = threadIdx.x;
    int tx = tid & 15, ty = tid >> 4;

    {
        const float* src = g_head + (size_t)r0 * DKK;
        #pragma unroll
        for (int l = 0; l < 4; l++) {
            int f = tid + l * 256;
            int row = f >> 4, c4 = (f & 15) * 4;
            float4 x = *(const float4*)&src[(size_t)row * 64 + c4];
            Hs[c4+0][row] = x.x; Hs[c4+1][row] = x.y;
            Hs[c4+2][row] = x.z; Hs[c4+3][row] = x.w;
        }
    }
    #pragma unroll
    for (int l = 0; l < 4; l++) {
        int f = tid + l * 256;
        int kk = f >> 4, c4 = (f & 15) * 4;
        *(float4*)&Ws[kk][c4] = *(const float4*)&Wo[(size_t)kk * DD + d0 + c4];
    }
    __syncthreads();

    float acc[4][4] = {};
    #pragma unroll 16
    for (int kk = 0; kk < 64; kk++) {
        float4 a  = *(const float4*)&Hs[kk][ty * 4];
        float4 bb = *(const float4*)&Ws[kk][tx * 4];
        float av[4] = {a.x, a.y, a.z, a.w};
        float bv[4] = {bb.x, bb.y, bb.z, bb.w};
        #pragma unroll
        for (int i = 0; i < 4; i++)
            #pragma unroll
            for (int j = 0; j < 4; j++)
                acc[i][j] = fmaf(av[i], bv[j], acc[i][j]);
    }
    #pragma unroll
    for (int i = 0; i < 4; i++) {
        float4 o; o.x = acc[i][0]; o.y = acc[i][1]; o.z = acc[i][2]; o.w = acc[i][3];
        *(float4*)&out[(size_t)(r0 + ty * 4 + i) * DD + d0 + tx * 4] = o;
    }
}

// ================= launch =================
extern "C" void kernel_launch(void* const* d_in, const int* in_sizes, int n_in,
                              void* d_out, int out_size) {
    const float* q  = (const float*)d_in[0];
    const float* k  = (const float*)d_in[1];
    const float* v  = (const float*)d_in[2];
    const float* Wq = (const float*)d_in[3];
    const float* Wk = (const float*)d_in[4];
    const float* Wv = (const float*)d_in[5];
    const float* Wo = (const float*)d_in[6];
    float* out = (float*)d_out;

    const int smem_proj   = (128*36 + 32*136) * 4;
    const int smem_rowsum = (128*68 + 64*68) * 4 + 2*128*4;
    const int smem_attn   = (128*68 + 64*68) * 4;
    cudaFuncSetAttribute(k_proj_mma, cudaFuncAttributeMaxDynamicSharedMemorySize, smem_proj);
    cudaFuncSetAttribute(k_rowsum,   cudaFuncAttributeMaxDynamicSharedMemorySize, smem_rowsum);
    cudaFuncSetAttribute(k_attn,     cudaFuncAttributeMaxDynamicSharedMemorySize, smem_attn);

    dim3 gp(DD / 128, SS / 128, 4);          // 2 kinds x 2 batches
    k_proj_mma<<<gp, 256, smem_proj>>>(q, k, Wq, Wk);

    dim3 gv(SS / 64, 1, BB);
    k_projv<<<gv, 256>>>(v, Wv);

    dim3 gr(SS / 128, HH, BB);
    k_rowsum<<<gr, 256, smem_rowsum>>>();

    dim3 ga(SS / 64, SS / 128, BB);
    k_attn<<<ga, 256, smem_attn>>>(out);

    dim3 gh(KSPLIT, SS / 64, BB);
    k_headp<<<gh, 256>>>(out);

    int n4 = BB * SS * DKK / 4;
    k_reduce<<<(n4 + 255) / 256, 256>>>();

    dim3 go(DD / 64, BB * SS / 64);
    k_out<<<go, 256>>>(Wo, out);
}